// round 12
// baseline (speedup 1.0000x reference)
#include <cuda_runtime.h>
#include <math.h>

#define NN 3000
#define EE 48000
#define FF 32
#define GRID 32
#define TPB 1024
#define EXCL 1200
#define KSELF 10800.0f
#define ROWCAP 64
#define NBAR 6u

// ---------------- global state ----------------
__device__ unsigned int g_gen[(size_t)NN * NN];   // dedup generations (never zeroed)
__device__ unsigned int g_run;
__device__ int g_deg[NN];
__device__ int g_rcnt[NN];
__device__ unsigned short g_cols[NN * ROWCAP];
__device__ float g_Y1r[NN * FF];                   // row-major publish buffers
__device__ float g_Y2r[NN * FF];
__device__ float g_X1r[NN * FF];
__device__ unsigned long long g_keys[NN];
__device__ float g_part[GRID * FF];
__device__ unsigned int g_root;                    // ticket barrier counter

// ---------------- smem layout (bytes) ----------------
#define OFF_ROWPTR 0                 // int[3008]
#define OFF_INVD   12032             // float[3008]
#define OFF_SINV   24064             // float[3008]
#define OFF_XCOL   36096             // float[3008]
#define OFF_Y1COL  48128             // float[3008]
#define OFF_YCUR   60160             // float[3008]   (scan scratch 'loc' spans YCUR..BJ)
#define OFF_BJ     72192             // float[3008]
#define OFF_TA     84224             // float[3008]   (scan 'part' / sW / spart alias)
#define OFF_TB     96256             // float[3008]   (sW spillover alias)
#define OFF_CIDX   108288            // ushort[48640] (keys alias at rank)
#define SMEM_TOTAL (108288 + 48640 * 2)   // 205568 B

// ---------------- flat ticket barrier (R5 flavor, 32 participants) ----------------
__device__ __forceinline__ void gsync(unsigned int epoch) {
    __syncthreads();
    if (threadIdx.x == 0) {
        asm volatile("red.release.gpu.global.add.u32 [%0], 1;" :: "l"(&g_root) : "memory");
        const unsigned int target = epoch * GRID;
        unsigned int v;
        do {
            asm volatile("ld.acquire.gpu.global.u32 %0, [%1];" : "=r"(v) : "l"(&g_root) : "memory");
        } while ((int)(v - target) < 0);
    }
    __syncthreads();
}

__device__ __forceinline__ unsigned int f2ord(float f) {
    unsigned int u = __float_as_uint(f);
    return (u & 0x80000000u) ? ~u : (u | 0x80000000u);
}

// ---------------- the one persistent kernel ----------------
__global__ void __launch_bounds__(TPB, 1)
cayley_all(const float* __restrict__ x, const int* __restrict__ ei,
           const float* __restrict__ ph, const float* __restrict__ palpha,
           const float* __restrict__ Wr0, const float* __restrict__ Wc0a,
           const float* __restrict__ Wc0b, const float* __restrict__ Wr1,
           const float* __restrict__ Wc1a, const float* __restrict__ Wc1b,
           const float* __restrict__ pw, const float* __restrict__ lw,
           const float* __restrict__ lb, float* __restrict__ out) {
    extern __shared__ __align__(16) unsigned char smem[];
    int*            rowptr = (int*)(smem + OFF_ROWPTR);
    float*          invD   = (float*)(smem + OFF_INVD);
    float*          sinv   = (float*)(smem + OFF_SINV);
    float*          xcol   = (float*)(smem + OFF_XCOL);
    float*          y1col  = (float*)(smem + OFF_Y1COL);
    float*          ycur   = (float*)(smem + OFF_YCUR);
    float*          bj     = (float*)(smem + OFF_BJ);
    float*          tA     = (float*)(smem + OFF_TA);
    float*          tB     = (float*)(smem + OFF_TB);
    unsigned short* cidx   = (unsigned short*)(smem + OFF_CIDX);

    const int tid  = threadIdx.x;
    const int lane = tid & 31;
    const int wid  = tid >> 5;
    const int bid  = blockIdx.x;       // = feature column owned by this block

    // row chunk for outgemm/finale: blocks 0..23 get 94 rows, 24..31 get 93
    const int gr0 = (bid < 24) ? bid * 94 : 2256 + (bid - 24) * 93;
    const int gnr = (bid < 24) ? 94 : 93;

    const unsigned int runv = g_run;
    const unsigned int gen  = runv + 1u;
    unsigned int epoch = runv * NBAR;

    const int* rowp = ei;
    const int* colp = ei + EE;
    const float hh = __ldg(ph);
    const float aa = __ldg(palpha);

    float pwv = __ldg(pw + lane);
    float nv = pwv * pwv;
#pragma unroll
    for (int o = 16; o > 0; o >>= 1) nv += __shfl_xor_sync(0xffffffffu, nv, o);
    const float pnorm = sqrtf(nv);

    // ---- S1: distributed edge build ----
    for (int e = bid * TPB + tid; e < EE; e += GRID * TPB) {
        int r = __ldg(rowp + e), c = __ldg(colp + e);
        atomicAdd(&g_deg[r], 1);
        unsigned int old = atomicMax(&g_gen[(size_t)r * NN + c], gen);
        if (old < gen) {
            int pos = atomicAdd(&g_rcnt[r], 1);
            if (pos < ROWCAP) g_cols[r * ROWCAP + pos] = (unsigned short)c;
        }
    }
    gsync(++epoch);   // B1

    // ---- pack CSR into smem: prefix sum + copy + per-node scalars + xcol ----
    {
        int* loc  = (int*)(smem + OFF_YCUR);   // 3072 ints (spans ycur+bj head)
        int* part = (int*)(smem + OFF_TA);     // 1024 ints
        for (int i = tid; i < NN; i += TPB) {
            int c2 = g_rcnt[i];
            loc[i] = c2 > ROWCAP ? ROWCAP : c2;
        }
        for (int i = NN + tid; i < 3072; i += TPB) loc[i] = 0;
        __syncthreads();
        int base = 3 * tid;
        int a0 = loc[base], a1 = loc[base + 1], a2 = loc[base + 2];
        part[tid] = a0 + a1 + a2;
        __syncthreads();
        for (int off = 1; off < TPB; off <<= 1) {
            int v = part[tid];
            int ad = (tid >= off) ? part[tid - off] : 0;
            __syncthreads();
            part[tid] = v + ad;
            __syncthreads();
        }
        int excl = (tid == 0) ? 0 : part[tid - 1];
        if (base < NN)     rowptr[base]     = excl;
        if (base + 1 < NN) rowptr[base + 1] = excl + a0;
        if (base + 2 < NN) rowptr[base + 2] = excl + a0 + a1;
        if (tid == TPB - 1) rowptr[NN] = part[TPB - 1];
        __syncthreads();
        // copy packed column indices
        for (int r = tid; r < NN; r += TPB) {
            int c2 = g_rcnt[r]; c2 = c2 > ROWCAP ? ROWCAP : c2;
            int dst = rowptr[r];
            for (int j = 0; j < c2; ++j)
                cidx[dst + j] = g_cols[r * ROWCAP + j];
        }
        // scalars + input column extract
        for (int i = tid; i < NN; i += TPB) {
            float d = (float)g_deg[i] - aa;
            sinv[i] = 1.0f / d;
            invD[i] = 1.0f / (d * hh);
            xcol[i] = __ldg(x + i * FF + bid);
        }
        __syncthreads();
    }

    // ---- smem SpMM sub-phase helpers ----
#define SBJAC(Y, OUTB) do { \
        _Pragma("unroll") \
        for (int s = 0; s < 3; ++s) { \
            int i = tid + s * TPB; \
            if (i < NN) { \
                int p0 = rowptr[i], p1 = rowptr[i + 1]; \
                float acc = 0.f; \
                _Pragma("unroll 8") \
                for (int p = p0; p < p1; ++p) acc += (Y)[cidx[p]]; \
                (OUTB)[i] = (Y)[i] - sinv[i] * acc; \
            } \
        } \
        __syncthreads(); } while (0)

#define SJAC(YK, OUTB) do { \
        _Pragma("unroll") \
        for (int s = 0; s < 3; ++s) { \
            int i = tid + s * TPB; \
            if (i < NN) { \
                int p0 = rowptr[i], p1 = rowptr[i + 1]; \
                float acc = 0.f; \
                _Pragma("unroll 8") \
                for (int p = p0; p < p1; ++p) { int c = cidx[p]; acc += invD[c] * (YK)[c]; } \
                (OUTB)[i] = acc + bj[i]; \
            } \
        } \
        __syncthreads(); } while (0)

#define ORDER(Y, O) do { SBJAC(Y, bj); SJAC(bj, tA); SJAC(tA, tB); \
                         SJAC(tB, tA); SJAC(tA, tB); SJAC(tB, O); } while (0)

    float myxout[3] = {0.f, 0.f, 0.f};
    float myscore[3] = {0.f, 0.f, 0.f};

    // ================= layer 0 (all column-local, zero global syncs) =================
    ORDER(xcol, y1col);
    ORDER(y1col, ycur);
    // publish Y1, Y2 columns (row-major scatter)
    for (int i = tid; i < NN; i += TPB) {
        g_Y1r[i * FF + bid] = y1col[i];
        g_Y2r[i * FF + bid] = ycur[i];
    }
    gsync(++epoch);   // B2
    // outgemm (row-partitioned) -> g_X1r
    {
        float* sW = tA;   // 12288B spans tA+tB (both dead)
        for (int t = tid; t < FF * FF; t += TPB) {
            int f = t >> 5, k = t & 31;
            sW[k * FF + f]        = __ldg(Wr0 + t);
            sW[1024 + k * FF + f] = __ldg(Wc0a + t);
            sW[2048 + k * FF + f] = __ldg(Wc0b + t);
        }
        __syncthreads();
#pragma unroll
        for (int t = 0; t < 3; ++t) {
            int lr = wid + t * 32;
            if (lr < gnr) {
                int r = gr0 + lr;
                float xo  = __ldg(x + r * FF + lane);
                float y1o = __ldcg(g_Y1r + r * FF + lane);
                float y2o = __ldcg(g_Y2r + r * FF + lane);
                float acc = 0.f;
#pragma unroll
                for (int k = 0; k < FF; ++k) {
                    float xv  = __shfl_sync(0xffffffffu, xo, k);
                    float y1v = __shfl_sync(0xffffffffu, y1o, k);
                    float y2v = __shfl_sync(0xffffffffu, y2o, k);
                    acc += xv * sW[k * FF + lane]
                         + 2.f * y1v * sW[1024 + k * FF + lane]
                         + 2.f * y2v * sW[2048 + k * FF + lane];
                }
                g_X1r[r * FF + lane] = fmaxf(acc, 0.f);
            }
        }
        gsync(++epoch);   // B3
    }
    // extract X1 column for layer 1
    for (int i = tid; i < NN; i += TPB)
        xcol[i] = __ldcg(g_X1r + i * FF + bid);
    __syncthreads();

    // ================= layer 1 =================
    ORDER(xcol, y1col);
    ORDER(y1col, ycur);
    for (int i = tid; i < NN; i += TPB) {
        g_Y1r[i * FF + bid] = y1col[i];
        g_Y2r[i * FF + bid] = ycur[i];
    }
    gsync(++epoch);   // B4
    // outgemm + scores/keys (X2 stays in registers)
    {
        float* sW = tA;
        for (int t = tid; t < FF * FF; t += TPB) {
            int f = t >> 5, k = t & 31;
            sW[k * FF + f]        = __ldg(Wr1 + t);
            sW[1024 + k * FF + f] = __ldg(Wc1a + t);
            sW[2048 + k * FF + f] = __ldg(Wc1b + t);
        }
        __syncthreads();
#pragma unroll
        for (int t = 0; t < 3; ++t) {
            int lr = wid + t * 32;
            if (lr < gnr) {
                int r = gr0 + lr;
                float xo  = __ldcg(g_X1r + r * FF + lane);
                float y1o = __ldcg(g_Y1r + r * FF + lane);
                float y2o = __ldcg(g_Y2r + r * FF + lane);
                float acc = 0.f;
#pragma unroll
                for (int k = 0; k < FF; ++k) {
                    float xv  = __shfl_sync(0xffffffffu, xo, k);
                    float y1v = __shfl_sync(0xffffffffu, y1o, k);
                    float y2v = __shfl_sync(0xffffffffu, y2o, k);
                    acc += xv * sW[k * FF + lane]
                         + 2.f * y1v * sW[1024 + k * FF + lane]
                         + 2.f * y2v * sW[2048 + k * FF + lane];
                }
                myxout[t] = fmaxf(acc, 0.f);
                float v = myxout[t] * pwv;
#pragma unroll
                for (int o = 16; o > 0; o >>= 1) v += __shfl_xor_sync(0xffffffffu, v, o);
                myscore[t] = tanhf(v / pnorm);
                if (lane == 0)
                    g_keys[r] = ((unsigned long long)f2ord(myscore[t]) << 32)
                              | (unsigned long long)(0xFFFFFFFFu - (unsigned int)r);
            }
        }
        gsync(++epoch);   // B5
    }

    // ---- rank + weighted partials + counter re-zero ----
    {
        unsigned long long* sk = (unsigned long long*)(smem + OFF_CIDX);  // cidx dead
        float* spart = (float*)(smem + OFF_Y1COL);                        // dead
        for (int i = tid; i < NN; i += TPB)
            sk[i] = __ldcg((const unsigned long long*)(g_keys + i));
        for (int t = tid; t < gnr; t += TPB) { g_deg[gr0 + t] = 0; g_rcnt[gr0 + t] = 0; }
        __syncthreads();
        float contrib = 0.f;
#pragma unroll
        for (int t = 0; t < 3; ++t) {
            int lr = wid + t * 32;
            if (lr < gnr) {
                int r = gr0 + lr;
                unsigned long long ki = ((unsigned long long)f2ord(myscore[t]) << 32)
                                      | (unsigned long long)(0xFFFFFFFFu - (unsigned int)r);
                int c2 = 0;
                for (int j = lane; j < NN; j += 32) c2 += (sk[j] < ki) ? 1 : 0;
#pragma unroll
                for (int o = 16; o > 0; o >>= 1) c2 += __shfl_xor_sync(0xffffffffu, c2, o);
                float coef = (c2 < EXCL && myscore[t] < 0.f) ? 0.f : myscore[t];
                contrib += coef * myxout[t];
            }
        }
        spart[wid * FF + lane] = contrib;
        __syncthreads();
        if (wid == 0) {
            float s2 = 0.f;
#pragma unroll
            for (int q = 0; q < 32; ++q) s2 += spart[q * FF + lane];
            g_part[bid * FF + lane] = s2;
        }
        gsync(++epoch);   // B6
    }

    // ---- block 0: final reduce + linear + epoch bump ----
    if (bid == 0) {
        if (wid == 0) {
            float s2 = 0.f;
#pragma unroll
            for (int q = 0; q < GRID; ++q) s2 += __ldcg(g_part + q * FF + lane);
            float* sg = (float*)(smem + OFF_Y1COL);
            sg[lane] = s2 * (1.0f / KSELF);
            __syncwarp();
            if (lane < 8) {
                float o = __ldg(lb + lane);
#pragma unroll
                for (int f = 0; f < FF; ++f) o += sg[f] * __ldg(lw + lane * FF + f);
                out[lane] = o;
            }
            if (lane == 0) g_run = gen;
        }
    }
}

// ---------------- host side ----------------
extern "C" void kernel_launch(void* const* d_in, const int* in_sizes, int n_in,
                              void* d_out, int out_size) {
    const float* x     = (const float*)d_in[0];
    const int*   ei    = (const int*)d_in[1];
    const float* h     = (const float*)d_in[2];
    const float* alpha = (const float*)d_in[3];
    const float* Wr0   = (const float*)d_in[4];
    const float* Wc0a  = (const float*)d_in[5];
    const float* Wc0b  = (const float*)d_in[6];
    const float* Wr1   = (const float*)d_in[7];
    const float* Wc1a  = (const float*)d_in[8];
    const float* Wc1b  = (const float*)d_in[9];
    const float* pw    = (const float*)d_in[10];
    const float* lw    = (const float*)d_in[11];
    const float* lb    = (const float*)d_in[12];

    cudaFuncSetAttribute(cayley_all, cudaFuncAttributeMaxDynamicSharedMemorySize, SMEM_TOTAL);
    cayley_all<<<GRID, TPB, SMEM_TOTAL>>>(x, ei, h, alpha, Wr0, Wc0a, Wc0b,
                                          Wr1, Wc1a, Wc1b, pw, lw, lb, (float*)d_out);
}

// round 13
// speedup vs baseline: 2.7394x; 2.7394x over previous
#include <cuda_runtime.h>
#include <math.h>

#define NN 3000
#define EE 48000
#define FF 32
#define GRID 128
#define CLUST 4
#define NCLUST 32          // global barrier participants
#define TPB 768            // 24 warps
#define NWARP 24
#define EXCL 1200
#define KSELF 10800.0f
#define ROWCAP 64
#define NRMAX 24
#define NBAR 26u           // must equal number of gsync calls per run

// ---------------- static global state ----------------
__device__ unsigned int g_gen[(size_t)NN * NN];   // 36 MB dedup generations (never zeroed)
__device__ unsigned int g_run;                     // run epoch
__device__ int g_deg[NN];
__device__ int g_rcnt[NN];
__device__ unsigned short g_cols[NN * ROWCAP];
__device__ float g_A[NN * FF];
__device__ float g_B[NN * FF];
__device__ float g_C[NN * FF];
__device__ float g_Y1[NN * FF];
__device__ float g_X1[NN * FF];
__device__ unsigned long long g_keys[NN];
__device__ float g_part[GRID * FF];
__device__ unsigned int g_root;                    // ticket counter (monotonic)

// ---------------- cluster-accelerated hierarchical barrier ----------------
__device__ __forceinline__ unsigned int ctarank() {
    unsigned int r;
    asm("mov.u32 %0, %%cluster_ctarank;" : "=r"(r));
    return r;
}

__device__ __forceinline__ void gsync(unsigned int epoch, unsigned int crank) {
    asm volatile("barrier.cluster.arrive.aligned;" ::: "memory");
    asm volatile("barrier.cluster.wait.aligned;" ::: "memory");
    if (crank == 0 && threadIdx.x == 0) {
        asm volatile("red.release.gpu.global.add.u32 [%0], 1;" :: "l"(&g_root) : "memory");
        const unsigned int target = epoch * NCLUST;
        unsigned int v;
        do {
            asm volatile("ld.acquire.gpu.global.u32 %0, [%1];" : "=r"(v) : "l"(&g_root) : "memory");
        } while ((int)(v - target) < 0);
    }
    asm volatile("barrier.cluster.arrive.aligned;" ::: "memory");
    asm volatile("barrier.cluster.wait.aligned;" ::: "memory");
}

__device__ __forceinline__ unsigned int f2ord(float f) {
    unsigned int u = __float_as_uint(f);
    return (u & 0x80000000u) ? ~u : (u | 0x80000000u);
}

// ---------------- the one persistent kernel ----------------
__global__ void __launch_bounds__(TPB, 1) __cluster_dims__(CLUST, 1, 1)
cayley_all(const float* __restrict__ x, const int* __restrict__ ei,
           const float* __restrict__ ph, const float* __restrict__ palpha,
           const float* __restrict__ Wr0, const float* __restrict__ Wc0a,
           const float* __restrict__ Wc0b, const float* __restrict__ Wr1,
           const float* __restrict__ Wc1a, const float* __restrict__ Wc1b,
           const float* __restrict__ pw, const float* __restrict__ lw,
           const float* __restrict__ lb, float* __restrict__ out) {
    // s_raw: 6 weight matrices (24576B) during phases (keys alias at rank), then partials after
    __shared__ __align__(16) unsigned char s_raw[24576 + NWARP * FF * 4];
    __shared__ __align__(8) float2 s_ew[NRMAX * ROWCAP];
    __shared__ int s_cnt[NRMAX];
    __shared__ float s_sinv[NRMAX];

    const int tid  = threadIdx.x;
    const int lane = tid & 31;
    const int wid  = tid >> 5;
    const int bid  = blockIdx.x;
    const unsigned int crank = ctarank();

    // balanced rows: blocks 0..55 get 24 rows, 56..127 get 23  (56*24 + 72*23 = 3000)
    const int r0    = (bid < 56) ? bid * 24 : 1344 + (bid - 56) * 23;
    const int nrows = (bid < 56) ? 24 : 23;

    const unsigned int runv = g_run;          // kernel-boundary safe
    const unsigned int gen  = runv + 1u;
    unsigned int epoch = runv * NBAR;

    const int* rowp = ei;
    const int* colp = ei + EE;
    const float hh = __ldg(ph);
    const float aa = __ldg(palpha);

    // pool_w norm
    float pwv = __ldg(pw + lane);
    float nv = pwv * pwv;
#pragma unroll
    for (int o = 16; o > 0; o >>= 1) nv += __shfl_xor_sync(0xffffffffu, nv, o);
    const float pnorm = sqrtf(nv);

    // ---- stage all 6 weight matrices (transposed) once; covered by B1 ----
    {
        float* sW = (float*)s_raw;
        for (int t = tid; t < FF * FF; t += TPB) {
            int f = t >> 5, k = t & 31;
            sW[k * FF + f]        = __ldg(Wr0 + t);
            sW[1024 + k * FF + f] = __ldg(Wc0a + t);
            sW[2048 + k * FF + f] = __ldg(Wc0b + t);
            sW[3072 + k * FF + f] = __ldg(Wr1 + t);
            sW[4096 + k * FF + f] = __ldg(Wc1a + t);
            sW[5120 + k * FF + f] = __ldg(Wc1b + t);
        }
    }

    // ---- S1: distributed edge build (1 edge / thread; GRID*TPB = 98304 >= EE) ----
    {
        int e = bid * TPB + tid;
        if (e < EE) {
            int r = __ldg(rowp + e), c = __ldg(colp + e);
            atomicAdd(&g_deg[r], 1);
            unsigned int old = atomicMax(&g_gen[(size_t)r * NN + c], gen);
            if (old < gen) {
                int pos = atomicAdd(&g_rcnt[r], 1);
                if (pos < ROWCAP) g_cols[r * ROWCAP + pos] = (unsigned short)c;
            }
        }
    }
    gsync(++epoch, crank);   // B1

    // ---- CSR -> smem + weights ----
    {
        if (tid < nrows) {
            int r = r0 + tid;
            int c2 = g_rcnt[r];
            s_cnt[tid] = c2 > ROWCAP ? ROWCAP : c2;
            s_sinv[tid] = 1.0f / ((float)g_deg[r] - aa);
        }
        __syncthreads();
        for (int idx = tid; idx < NRMAX * ROWCAP; idx += TPB) {
            int lr = idx >> 6, j = idx & 63;
            if (lr < nrows && j < s_cnt[lr]) {
                int c = (int)g_cols[(r0 + lr) * ROWCAP + j];
                float w = 1.0f / (((float)g_deg[c] - aa) * hh);
                s_ew[idx] = make_float2(__int_as_float(c * (FF * 4)), w);
            }
        }
        __syncthreads();
    }

#define ROW_BJAC(IN, RES) do { \
        int r = r0 + wid; \
        float diag = __ldcg((IN) + r * FF + lane); \
        int cnt = s_cnt[wid]; \
        const float2* ep = s_ew + wid * ROWCAP; \
        float acc = 0.f; \
        _Pragma("unroll 8") \
        for (int j = 0; j < cnt; ++j) { \
            float2 e = ep[j]; \
            acc += __ldcg((const float*)((const char*)(IN) + __float_as_int(e.x)) + lane); \
        } \
        RES = diag - s_sinv[wid] * acc; \
    } while (0)

#define ROW_JACR(YK, BJREG, RES) do { \
        int cnt = s_cnt[wid]; \
        const float2* ep = s_ew + wid * ROWCAP; \
        float acc = 0.f; \
        _Pragma("unroll 8") \
        for (int j = 0; j < cnt; ++j) { \
            float2 e = ep[j]; \
            acc += e.y * __ldcg((const float*)((const char*)(YK) + __float_as_int(e.x)) + lane); \
        } \
        RES = acc + (BJREG); \
    } while (0)

#define PHASE_BJAC(IN, OUT, BJREG) do { \
        if (wid < nrows) { ROW_BJAC(IN, BJREG); \
            OUT[(r0 + wid) * FF + lane] = BJREG; } \
        gsync(++epoch, crank); } while (0)

#define PHASE_JAC(YK, BJREG, OUT) do { \
        if (wid < nrows) { float rres; ROW_JACR(YK, BJREG, rres); \
            OUT[(r0 + wid) * FF + lane] = rres; } \
        gsync(++epoch, crank); } while (0)

    float myscore = 0.f, myxout = 0.f;
    float bjv = 0.f;
    const float* sW = (const float*)s_raw;

    // ---- layer 0 order 0 ----
    PHASE_BJAC(x, g_A, bjv);       // B2
    PHASE_JAC(g_A, bjv, g_B);      // B3
    PHASE_JAC(g_B, bjv, g_C);      // B4
    PHASE_JAC(g_C, bjv, g_B);      // B5
    PHASE_JAC(g_B, bjv, g_C);      // B6
    PHASE_JAC(g_C, bjv, g_Y1);     // B7

    // ---- layer 0 order 1 ----
    PHASE_BJAC(g_Y1, g_A, bjv);    // B8
    PHASE_JAC(g_A, bjv, g_B);      // B9
    PHASE_JAC(g_B, bjv, g_C);      // B10
    PHASE_JAC(g_C, bjv, g_B);      // B11
    PHASE_JAC(g_B, bjv, g_C);      // B12
    // fused last jac + outgemm -> X1
    {
        if (wid < nrows) {
            int r = r0 + wid;
            float y2; ROW_JACR(g_C, bjv, y2);
            float y1 = __ldcg(g_Y1 + r * FF + lane);
            float xo = __ldg(x + r * FF + lane);
            float acc = 0.f;
#pragma unroll
            for (int k = 0; k < FF; ++k) {
                float xv  = __shfl_sync(0xffffffffu, xo, k);
                float y1v = __shfl_sync(0xffffffffu, y1, k);
                float y2v = __shfl_sync(0xffffffffu, y2, k);
                acc += xv * sW[k * FF + lane]
                     + 2.f * y1v * sW[1024 + k * FF + lane]
                     + 2.f * y2v * sW[2048 + k * FF + lane];
            }
            g_X1[r * FF + lane] = fmaxf(acc, 0.f);
        }
        gsync(++epoch, crank);   // B13
    }

    // ---- layer 1 order 0 ----
    PHASE_BJAC(g_X1, g_A, bjv);    // B14
    PHASE_JAC(g_A, bjv, g_B);      // B15
    PHASE_JAC(g_B, bjv, g_C);      // B16
    PHASE_JAC(g_C, bjv, g_B);      // B17
    PHASE_JAC(g_B, bjv, g_C);      // B18
    PHASE_JAC(g_C, bjv, g_Y1);     // B19

    // ---- layer 1 order 1 ----
    PHASE_BJAC(g_Y1, g_A, bjv);    // B20
    PHASE_JAC(g_A, bjv, g_B);      // B21
    PHASE_JAC(g_B, bjv, g_C);      // B22
    PHASE_JAC(g_C, bjv, g_B);      // B23
    PHASE_JAC(g_B, bjv, g_C);      // B24
    // fused last jac + outgemm + score/keys (X2 stays in registers)
    {
        if (wid < nrows) {
            int r = r0 + wid;
            float y2; ROW_JACR(g_C, bjv, y2);
            float y1 = __ldcg(g_Y1 + r * FF + lane);
            float xo = __ldcg(g_X1 + r * FF + lane);
            float acc = 0.f;
#pragma unroll
            for (int k = 0; k < FF; ++k) {
                float xv  = __shfl_sync(0xffffffffu, xo, k);
                float y1v = __shfl_sync(0xffffffffu, y1, k);
                float y2v = __shfl_sync(0xffffffffu, y2, k);
                acc += xv * sW[3072 + k * FF + lane]
                     + 2.f * y1v * sW[4096 + k * FF + lane]
                     + 2.f * y2v * sW[5120 + k * FF + lane];
            }
            myxout = fmaxf(acc, 0.f);
            float v = myxout * pwv;
#pragma unroll
            for (int o = 16; o > 0; o >>= 1) v += __shfl_xor_sync(0xffffffffu, v, o);
            myscore = tanhf(v / pnorm);
            if (lane == 0)
                g_keys[r] = ((unsigned long long)f2ord(myscore) << 32)
                          | (unsigned long long)(0xFFFFFFFFu - (unsigned int)r);
        }
        gsync(++epoch, crank);   // B25
    }

    // ---- rank + weighted partial sums + counter re-zero for next run ----
    {
        unsigned long long* sk = (unsigned long long*)s_raw;   // weights dead now
        float* spart = (float*)(s_raw + 24576);
        for (int i = tid; i < NN; i += TPB)
            sk[i] = __ldcg((const unsigned long long*)(g_keys + i));
        if (tid < nrows) { g_deg[r0 + tid] = 0; g_rcnt[r0 + tid] = 0; }
        __syncthreads();
        float contrib = 0.f;
        if (wid < nrows) {
            int r = r0 + wid;
            unsigned long long ki = ((unsigned long long)f2ord(myscore) << 32)
                                  | (unsigned long long)(0xFFFFFFFFu - (unsigned int)r);
            int c2 = 0;
            for (int j = lane; j < NN; j += 32) c2 += (sk[j] < ki) ? 1 : 0;
#pragma unroll
            for (int o = 16; o > 0; o >>= 1) c2 += __shfl_xor_sync(0xffffffffu, c2, o);
            float coef = (c2 < EXCL && myscore < 0.f) ? 0.f : myscore;
            contrib = coef * myxout;
        }
        spart[wid * FF + lane] = contrib;
        __syncthreads();
        if (wid == 0) {
            float t = 0.f;
#pragma unroll
            for (int q = 0; q < NWARP; ++q) t += spart[q * FF + lane];
            g_part[bid * FF + lane] = t;
        }
        gsync(++epoch, crank);   // B26
    }

    // ---- block 0: final reduce + linear + run-epoch bump ----
    if (bid == 0) {
        float* spart = (float*)(s_raw + 24576);
        float a = 0.f;
        for (int b = wid; b < GRID; b += NWARP) a += __ldcg(g_part + b * FF + lane);
        spart[wid * FF + lane] = a;
        __syncthreads();
        if (wid == 0) {
            float t = 0.f;
#pragma unroll
            for (int q = 0; q < NWARP; ++q) t += spart[q * FF + lane];
            spart[lane] = t * (1.0f / KSELF);
            __syncwarp();
            if (lane < 8) {
                float o = __ldg(lb + lane);
#pragma unroll
                for (int f = 0; f < FF; ++f) o += spart[f] * __ldg(lw + lane * FF + f);
                out[lane] = o;
            }
            if (lane == 0) g_run = gen;
        }
    }
}

// ---------------- host side ----------------
extern "C" void kernel_launch(void* const* d_in, const int* in_sizes, int n_in,
                              void* d_out, int out_size) {
    const float* x     = (const float*)d_in[0];
    const int*   ei    = (const int*)d_in[1];
    const float* h     = (const float*)d_in[2];
    const float* alpha = (const float*)d_in[3];
    const float* Wr0   = (const float*)d_in[4];
    const float* Wc0a  = (const float*)d_in[5];
    const float* Wc0b  = (const float*)d_in[6];
    const float* Wr1   = (const float*)d_in[7];
    const float* Wc1a  = (const float*)d_in[8];
    const float* Wc1b  = (const float*)d_in[9];
    const float* pw    = (const float*)d_in[10];
    const float* lw    = (const float*)d_in[11];
    const float* lb    = (const float*)d_in[12];

    cayley_all<<<GRID, TPB>>>(x, ei, h, alpha, Wr0, Wc0a, Wc0b,
                              Wr1, Wc1a, Wc1b, pw, lw, lb, (float*)d_out);
}

// round 14
// speedup vs baseline: 3.0307x; 1.1063x over previous
#include <cuda_runtime.h>
#include <math.h>

#define NN 3000
#define EE 48000
#define FF 32
#define GRID 148
#define TPB 672            // 21 warps
#define NWARP 21
#define EXCL 1200
#define KSELF 10800.0f
#define ROWCAP 64
#define NRMAX 21
#define NBAR 26u

// ---------------- static global state ----------------
__device__ unsigned int g_gen[(size_t)NN * NN];   // 36 MB dedup generations (never zeroed)
__device__ unsigned int g_run;                     // run epoch
__device__ int g_deg[NN];
__device__ int g_rcnt[NN];
__device__ unsigned short g_cols[NN * ROWCAP];
__device__ float g_A[NN * FF];
__device__ float g_B[NN * FF];
__device__ float g_C[NN * FF];
__device__ float g_Y1[NN * FF];
__device__ float g_X1[NN * FF];
__device__ unsigned long long g_keys[NN];
__device__ float g_part[GRID * FF];
__device__ unsigned int g_ctr;                     // ticket counter (monotonic)

// ---------------- ticket barrier: atomic arrive + RELAXED poll + one acquire fence ----------------
__device__ __forceinline__ void gsync() {
    __syncthreads();
    if (threadIdx.x == 0) {
        unsigned int old;
        asm volatile("atom.release.gpu.global.add.u32 %0, [%1], 1;"
                     : "=r"(old) : "l"(&g_ctr) : "memory");
        unsigned int target = old - (old % GRID) + GRID;   // next multiple of GRID
        unsigned int v;
        do {
            asm volatile("ld.relaxed.gpu.global.u32 %0, [%1];" : "=r"(v) : "l"(&g_ctr) : "memory");
        } while ((int)(v - target) < 0);
        asm volatile("fence.acq_rel.gpu;" ::: "memory");   // acquire: order subsequent reads
    }
    __syncthreads();
}

__device__ __forceinline__ unsigned int f2ord(float f) {
    unsigned int u = __float_as_uint(f);
    return (u & 0x80000000u) ? ~u : (u | 0x80000000u);
}

// ---------------- the one persistent kernel ----------------
__global__ void __launch_bounds__(TPB, 1)
cayley_all(const float* __restrict__ x, const int* __restrict__ ei,
           const float* __restrict__ ph, const float* __restrict__ palpha,
           const float* __restrict__ Wr0, const float* __restrict__ Wc0a,
           const float* __restrict__ Wc0b, const float* __restrict__ Wr1,
           const float* __restrict__ Wc1a, const float* __restrict__ Wc1b,
           const float* __restrict__ pw, const float* __restrict__ lw,
           const float* __restrict__ lb, float* __restrict__ out) {
    // s_raw: 6 weight matrices (24576B) during phases (keys alias at rank), then partials
    __shared__ __align__(16) unsigned char s_raw[24576 + NWARP * FF * 4];
    __shared__ __align__(8) float2 s_ew[NRMAX * ROWCAP];
    __shared__ int s_cnt[NRMAX];
    __shared__ float s_sinv[NRMAX];

    const int tid  = threadIdx.x;
    const int lane = tid & 31;
    const int wid  = tid >> 5;
    const int bid  = blockIdx.x;

    // balanced rows: blocks 0..39 get 21, 40..147 get 20
    const int r0    = (bid < 40) ? bid * 21 : 840 + (bid - 40) * 20;
    const int nrows = (bid < 40) ? 21 : 20;

    const unsigned int runv = g_run;          // kernel-boundary safe
    const unsigned int gen  = runv + 1u;

    const int* rowp = ei;
    const int* colp = ei + EE;
    const float hh = __ldg(ph);
    const float aa = __ldg(palpha);

    // pool_w norm
    float pwv = __ldg(pw + lane);
    float nv = pwv * pwv;
#pragma unroll
    for (int o = 16; o > 0; o >>= 1) nv += __shfl_xor_sync(0xffffffffu, nv, o);
    const float pnorm = sqrtf(nv);

    // ---- stage all 6 weight matrices (transposed) once; ordered by B1's syncthreads ----
    {
        float* sW = (float*)s_raw;
        for (int t = tid; t < FF * FF; t += TPB) {
            int f = t >> 5, k = t & 31;
            sW[k * FF + f]        = __ldg(Wr0 + t);
            sW[1024 + k * FF + f] = __ldg(Wc0a + t);
            sW[2048 + k * FF + f] = __ldg(Wc0b + t);
            sW[3072 + k * FF + f] = __ldg(Wr1 + t);
            sW[4096 + k * FF + f] = __ldg(Wc1a + t);
            sW[5120 + k * FF + f] = __ldg(Wc1b + t);
        }
    }

    // ---- S1: distributed edge build (1 edge / thread) ----
    {
        int e = bid * TPB + tid;
        if (e < EE) {
            int r = __ldg(rowp + e), c = __ldg(colp + e);
            atomicAdd(&g_deg[r], 1);
            unsigned int old = atomicMax(&g_gen[(size_t)r * NN + c], gen);
            if (old < gen) {
                int pos = atomicAdd(&g_rcnt[r], 1);
                if (pos < ROWCAP) g_cols[r * ROWCAP + pos] = (unsigned short)c;
            }
        }
    }
    gsync();   // B1

    // ---- CSR -> smem + weights ----
    {
        if (tid < nrows) {
            int r = r0 + tid;
            int c2 = g_rcnt[r];
            s_cnt[tid] = c2 > ROWCAP ? ROWCAP : c2;
            s_sinv[tid] = 1.0f / ((float)g_deg[r] - aa);
        }
        __syncthreads();
        for (int idx = tid; idx < NRMAX * ROWCAP; idx += TPB) {
            int lr = idx >> 6, j = idx & 63;
            if (lr < nrows && j < s_cnt[lr]) {
                int c = (int)g_cols[(r0 + lr) * ROWCAP + j];
                float w = 1.0f / (((float)g_deg[c] - aa) * hh);
                s_ew[idx] = make_float2(__int_as_float(c * (FF * 4)), w);
            }
        }
        __syncthreads();
    }

#define ROW_BJAC(IN, RES) do { \
        int r = r0 + wid; \
        float diag = __ldcg((IN) + r * FF + lane); \
        int cnt = s_cnt[wid]; \
        const float2* ep = s_ew + wid * ROWCAP; \
        float acc = 0.f; \
        _Pragma("unroll 8") \
        for (int j = 0; j < cnt; ++j) { \
            float2 e = ep[j]; \
            acc += __ldcg((const float*)((const char*)(IN) + __float_as_int(e.x)) + lane); \
        } \
        RES = diag - s_sinv[wid] * acc; \
    } while (0)

    // jac with b_j carried in register
#define ROW_JACR(YK, BJREG, RES) do { \
        int cnt = s_cnt[wid]; \
        const float2* ep = s_ew + wid * ROWCAP; \
        float acc = 0.f; \
        _Pragma("unroll 8") \
        for (int j = 0; j < cnt; ++j) { \
            float2 e = ep[j]; \
            acc += e.y * __ldcg((const float*)((const char*)(YK) + __float_as_int(e.x)) + lane); \
        } \
        RES = acc + (BJREG); \
    } while (0)

#define PHASE_BJAC(IN, OUT, BJREG) do { \
        if (wid < nrows) { ROW_BJAC(IN, BJREG); \
            OUT[(r0 + wid) * FF + lane] = BJREG; } \
        gsync(); } while (0)

#define PHASE_JAC(YK, BJREG, OUT) do { \
        if (wid < nrows) { float rres; ROW_JACR(YK, BJREG, rres); \
            OUT[(r0 + wid) * FF + lane] = rres; } \
        gsync(); } while (0)

    float myscore = 0.f, myxout = 0.f;
    float bjv = 0.f;
    const float* sW = (const float*)s_raw;

    // ---- layer 0 order 0 ----
    PHASE_BJAC(x, g_A, bjv);       // B2
    PHASE_JAC(g_A, bjv, g_B);      // B3
    PHASE_JAC(g_B, bjv, g_C);      // B4
    PHASE_JAC(g_C, bjv, g_B);      // B5
    PHASE_JAC(g_B, bjv, g_C);      // B6
    PHASE_JAC(g_C, bjv, g_Y1);     // B7

    // ---- layer 0 order 1 ----
    PHASE_BJAC(g_Y1, g_A, bjv);    // B8
    PHASE_JAC(g_A, bjv, g_B);      // B9
    PHASE_JAC(g_B, bjv, g_C);      // B10
    PHASE_JAC(g_C, bjv, g_B);      // B11
    PHASE_JAC(g_B, bjv, g_C);      // B12
    // fused last jac + outgemm -> X1
    {
        if (wid < nrows) {
            int r = r0 + wid;
            float y2; ROW_JACR(g_C, bjv, y2);
            float y1 = __ldcg(g_Y1 + r * FF + lane);
            float xo = __ldg(x + r * FF + lane);
            float acc = 0.f;
#pragma unroll
            for (int k = 0; k < FF; ++k) {
                float xv  = __shfl_sync(0xffffffffu, xo, k);
                float y1v = __shfl_sync(0xffffffffu, y1, k);
                float y2v = __shfl_sync(0xffffffffu, y2, k);
                acc += xv * sW[k * FF + lane]
                     + 2.f * y1v * sW[1024 + k * FF + lane]
                     + 2.f * y2v * sW[2048 + k * FF + lane];
            }
            g_X1[r * FF + lane] = fmaxf(acc, 0.f);
        }
        gsync();   // B13
    }

    // ---- layer 1 order 0 ----
    PHASE_BJAC(g_X1, g_A, bjv);    // B14
    PHASE_JAC(g_A, bjv, g_B);      // B15
    PHASE_JAC(g_B, bjv, g_C);      // B16
    PHASE_JAC(g_C, bjv, g_B);      // B17
    PHASE_JAC(g_B, bjv, g_C);      // B18
    PHASE_JAC(g_C, bjv, g_Y1);     // B19

    // ---- layer 1 order 1 ----
    PHASE_BJAC(g_Y1, g_A, bjv);    // B20
    PHASE_JAC(g_A, bjv, g_B);      // B21
    PHASE_JAC(g_B, bjv, g_C);      // B22
    PHASE_JAC(g_C, bjv, g_B);      // B23
    PHASE_JAC(g_B, bjv, g_C);      // B24
    // fused last jac + outgemm + score/keys (X2 stays in registers)
    {
        if (wid < nrows) {
            int r = r0 + wid;
            float y2; ROW_JACR(g_C, bjv, y2);
            float y1 = __ldcg(g_Y1 + r * FF + lane);
            float xo = __ldcg(g_X1 + r * FF + lane);
            float acc = 0.f;
#pragma unroll
            for (int k = 0; k < FF; ++k) {
                float xv  = __shfl_sync(0xffffffffu, xo, k);
                float y1v = __shfl_sync(0xffffffffu, y1, k);
                float y2v = __shfl_sync(0xffffffffu, y2, k);
                acc += xv * sW[3072 + k * FF + lane]
                     + 2.f * y1v * sW[4096 + k * FF + lane]
                     + 2.f * y2v * sW[5120 + k * FF + lane];
            }
            myxout = fmaxf(acc, 0.f);
            float v = myxout * pwv;
#pragma unroll
            for (int o = 16; o > 0; o >>= 1) v += __shfl_xor_sync(0xffffffffu, v, o);
            myscore = tanhf(v / pnorm);
            if (lane == 0)
                g_keys[r] = ((unsigned long long)f2ord(myscore) << 32)
                          | (unsigned long long)(0xFFFFFFFFu - (unsigned int)r);
        }
        gsync();   // B25
    }

    // ---- rank + weighted partial sums + counter re-zero for next run ----
    {
        unsigned long long* sk = (unsigned long long*)s_raw;   // weights dead now
        float* spart = (float*)(s_raw + 24576);
        for (int i = tid; i < NN; i += TPB)
            sk[i] = __ldcg((const unsigned long long*)(g_keys + i));
        if (tid < nrows) { g_deg[r0 + tid] = 0; g_rcnt[r0 + tid] = 0; }
        __syncthreads();
        float contrib = 0.f;
        if (wid < nrows) {
            int r = r0 + wid;
            unsigned long long ki = ((unsigned long long)f2ord(myscore) << 32)
                                  | (unsigned long long)(0xFFFFFFFFu - (unsigned int)r);
            int c2 = 0;
            for (int j = lane; j < NN; j += 32) c2 += (sk[j] < ki) ? 1 : 0;
#pragma unroll
            for (int o = 16; o > 0; o >>= 1) c2 += __shfl_xor_sync(0xffffffffu, c2, o);
            float coef = (c2 < EXCL && myscore < 0.f) ? 0.f : myscore;
            contrib = coef * myxout;
        }
        spart[wid * FF + lane] = contrib;
        __syncthreads();
        if (wid == 0) {
            float t = 0.f;
#pragma unroll
            for (int q = 0; q < NWARP; ++q) t += spart[q * FF + lane];
            g_part[bid * FF + lane] = t;
        }
        gsync();   // B26
    }

    // ---- block 0: final reduce + linear + run-epoch bump ----
    if (bid == 0) {
        float* spart = (float*)(s_raw + 24576);
        float a = 0.f;
        for (int b = wid; b < GRID; b += NWARP) a += __ldcg(g_part + b * FF + lane);
        spart[wid * FF + lane] = a;
        __syncthreads();
        if (wid == 0) {
            float t = 0.f;
#pragma unroll
            for (int q = 0; q < NWARP; ++q) t += spart[q * FF + lane];
            spart[lane] = t * (1.0f / KSELF);
            __syncwarp();
            if (lane < 8) {
                float o = __ldg(lb + lane);
#pragma unroll
                for (int f = 0; f < FF; ++f) o += spart[f] * __ldg(lw + lane * FF + f);
                out[lane] = o;
            }
            if (lane == 0) g_run = gen;
        }
    }
}

// ---------------- host side ----------------
extern "C" void kernel_launch(void* const* d_in, const int* in_sizes, int n_in,
                              void* d_out, int out_size) {
    const float* x     = (const float*)d_in[0];
    const int*   ei    = (const int*)d_in[1];
    const float* h     = (const float*)d_in[2];
    const float* alpha = (const float*)d_in[3];
    const float* Wr0   = (const float*)d_in[4];
    const float* Wc0a  = (const float*)d_in[5];
    const float* Wc0b  = (const float*)d_in[6];
    const float* Wr1   = (const float*)d_in[7];
    const float* Wc1a  = (const float*)d_in[8];
    const float* Wc1b  = (const float*)d_in[9];
    const float* pw    = (const float*)d_in[10];
    const float* lw    = (const float*)d_in[11];
    const float* lb    = (const float*)d_in[12];

    cayley_all<<<GRID, TPB>>>(x, ei, h, alpha, Wr0, Wc0a, Wc0b,
                              Wr1, Wc1a, Wc1b, pw, lw, lb, (float*)d_out);
}

// round 15
// speedup vs baseline: 3.2411x; 1.0694x over previous
#include <cuda_runtime.h>
#include <math.h>

#define NN 3000
#define EE 48000
#define FF 32
#define GRID 148
#define TPB 672            // 21 warps
#define NWARP 21
#define EXCL 1200
#define KSELF 10800.0f
#define ROWCAP 64
#define NRMAX 21

// ---------------- static global state ----------------
__device__ unsigned int g_gen[(size_t)NN * NN];   // 36 MB dedup generations (never zeroed)
__device__ unsigned int g_run;                     // run epoch (bumped by finalizer)
__device__ int g_deg[NN];                          // re-zeroed each run by owners
__device__ int g_rcnt[NN];
__device__ unsigned short g_cols[NN * ROWCAP];
__device__ float g_A[NN * FF];
__device__ float g_B[NN * FF];
__device__ float g_C[NN * FF];
__device__ float g_Y1[NN * FF];
__device__ float g_X1[NN * FF];
__device__ unsigned long long g_keys[NN];
__device__ float g_part[GRID * FF];
__device__ unsigned int g_ctr;                     // ticket barrier counter (monotonic)

// ---------------- R5 ticket barrier (measured optimum) ----------------
__device__ __forceinline__ void gsync() {
    __syncthreads();
    if (threadIdx.x == 0) {
        unsigned int old;
        asm volatile("atom.release.gpu.add.u32 %0, [%1], 1;"
                     : "=r"(old) : "l"(&g_ctr) : "memory");
        unsigned int target = old - (old % GRID) + GRID;   // next multiple of GRID
        unsigned int v;
        do {
            asm volatile("ld.acquire.gpu.u32 %0, [%1];" : "=r"(v) : "l"(&g_ctr) : "memory");
        } while ((int)(v - target) < 0);
    }
    __syncthreads();
}

__device__ __forceinline__ unsigned int f2ord(float f) {
    unsigned int u = __float_as_uint(f);
    return (u & 0x80000000u) ? ~u : (u | 0x80000000u);
}

// ---------------- the one persistent kernel ----------------
__global__ void __launch_bounds__(TPB, 1)
cayley_all(const float* __restrict__ x, const int* __restrict__ ei,
           const float* __restrict__ ph, const float* __restrict__ palpha,
           const float* __restrict__ Wr0, const float* __restrict__ Wc0a,
           const float* __restrict__ Wc0b, const float* __restrict__ Wr1,
           const float* __restrict__ Wc1a, const float* __restrict__ Wc1b,
           const float* __restrict__ pw, const float* __restrict__ lw,
           const float* __restrict__ lb, float* __restrict__ out) {
    __shared__ __align__(16) unsigned char s_raw[24000 + NWARP * FF * 4];  // keys / sW / partials
    __shared__ __align__(8) float2 s_ew[NRMAX * ROWCAP];   // (byte-offset bits, weight) per edge
    __shared__ int s_cnt[NRMAX];
    __shared__ float s_sinv[NRMAX];
    __shared__ int s_last;

    const int tid  = threadIdx.x;
    const int lane = tid & 31;
    const int wid  = tid >> 5;
    const int bid  = blockIdx.x;

    // balanced rows: blocks 0..39 get 21, 40..147 get 20
    const int r0    = (bid < 40) ? bid * 21 : 840 + (bid - 40) * 20;
    const int nrows = (bid < 40) ? 21 : 20;

    const unsigned int gen = g_run + 1u;     // unique per run (runs serialize)

    const int* rowp = ei;
    const int* colp = ei + EE;
    const float hh = __ldg(ph);
    const float aa = __ldg(palpha);

    // pool_w norm
    float pwv = __ldg(pw + lane);
    float nv = pwv * pwv;
#pragma unroll
    for (int o = 16; o > 0; o >>= 1) nv += __shfl_xor_sync(0xffffffffu, nv, o);
    const float pnorm = sqrtf(nv);

    // ---- S1: distributed edge build (1 edge / thread) ----
    {
        int e = bid * TPB + tid;
        if (e < EE) {
            int r = __ldg(rowp + e), c = __ldg(colp + e);
            atomicAdd(&g_deg[r], 1);                              // degree with multiplicity
            unsigned int old = atomicMax(&g_gen[(size_t)r * NN + c], gen);
            if (old < gen) {                                      // first occurrence this run
                int pos = atomicAdd(&g_rcnt[r], 1);
                if (pos < ROWCAP) g_cols[r * ROWCAP + pos] = (unsigned short)c;
            }
        }
    }
    gsync();   // B1

    // ---- CSR -> smem + weights ----
    {
        if (tid < nrows) {
            int r = r0 + tid;
            int c2 = g_rcnt[r];
            s_cnt[tid] = c2 > ROWCAP ? ROWCAP : c2;
            s_sinv[tid] = 1.0f / ((float)g_deg[r] - aa);
        }
        __syncthreads();
        for (int idx = tid; idx < NRMAX * ROWCAP; idx += TPB) {
            int lr = idx >> 6, j = idx & 63;
            if (lr < nrows && j < s_cnt[lr]) {
                int c = (int)g_cols[(r0 + lr) * ROWCAP + j];
                float w = 1.0f / (((float)g_deg[c] - aa) * hh);   // invD[col]
                s_ew[idx] = make_float2(__int_as_float(c * (FF * 4)), w);
            }
        }
        __syncthreads();
    }

#define ROW_BJAC(IN, RES) do { \
        int r = r0 + wid; \
        float diag = __ldcg((IN) + r * FF + lane); \
        int cnt = s_cnt[wid]; \
        const float2* ep = s_ew + wid * ROWCAP; \
        float acc = 0.f; \
        _Pragma("unroll 8") \
        for (int j = 0; j < cnt; ++j) { \
            float2 e = ep[j]; \
            acc += __ldcg((const float*)((const char*)(IN) + __float_as_int(e.x)) + lane); \
        } \
        RES = diag - s_sinv[wid] * acc; \
    } while (0)

#define ROW_JAC(YK, BJ, RES) do { \
        int r = r0 + wid; \
        float bjv = __ldcg((BJ) + r * FF + lane); \
        int cnt = s_cnt[wid]; \
        const float2* ep = s_ew + wid * ROWCAP; \
        float acc = 0.f; \
        _Pragma("unroll 8") \
        for (int j = 0; j < cnt; ++j) { \
            float2 e = ep[j]; \
            acc += e.y * __ldcg((const float*)((const char*)(YK) + __float_as_int(e.x)) + lane); \
        } \
        RES = acc + bjv; \
    } while (0)

#define PHASE_BJAC(IN, OUT) do { \
        if (wid < nrows) { float rres; ROW_BJAC(IN, rres); \
            OUT[(r0 + wid) * FF + lane] = rres; } \
        gsync(); } while (0)

#define PHASE_JAC(YK, BJ, OUT) do { \
        if (wid < nrows) { float rres; ROW_JAC(YK, BJ, rres); \
            OUT[(r0 + wid) * FF + lane] = rres; } \
        gsync(); } while (0)

    float myscore = 0.f, myxout = 0.f;

    // ---- layer 0 order 0 ----
    PHASE_BJAC(x, g_A);            // B2
    PHASE_JAC(g_A, g_A, g_B);      // B3
    PHASE_JAC(g_B, g_A, g_C);      // B4
    PHASE_JAC(g_C, g_A, g_B);      // B5
    PHASE_JAC(g_B, g_A, g_C);      // B6
    PHASE_JAC(g_C, g_A, g_Y1);     // B7

    // ---- layer 0 order 1 ----
    PHASE_BJAC(g_Y1, g_A);         // B8
    PHASE_JAC(g_A, g_A, g_B);      // B9
    PHASE_JAC(g_B, g_A, g_C);      // B10
    PHASE_JAC(g_C, g_A, g_B);      // B11
    PHASE_JAC(g_B, g_A, g_C);      // B12
    // fused last jac + outgemm -> X1
    {
        float* sW = (float*)s_raw;
        for (int t = tid; t < FF * FF; t += TPB) {
            int f = t >> 5, k = t & 31;
            sW[k * FF + f]        = __ldg(Wr0 + t);
            sW[1024 + k * FF + f] = __ldg(Wc0a + t);
            sW[2048 + k * FF + f] = __ldg(Wc0b + t);
        }
        __syncthreads();
        if (wid < nrows) {
            int r = r0 + wid;
            float y2; ROW_JAC(g_C, g_A, y2);
            float y1 = __ldcg(g_Y1 + r * FF + lane);
            float xo = __ldg(x + r * FF + lane);
            float acc = 0.f;
#pragma unroll
            for (int k = 0; k < FF; ++k) {
                float xv  = __shfl_sync(0xffffffffu, xo, k);
                float y1v = __shfl_sync(0xffffffffu, y1, k);
                float y2v = __shfl_sync(0xffffffffu, y2, k);
                acc += xv * sW[k * FF + lane]
                     + 2.f * y1v * sW[1024 + k * FF + lane]
                     + 2.f * y2v * sW[2048 + k * FF + lane];
            }
            g_X1[r * FF + lane] = fmaxf(acc, 0.f);
        }
        gsync();   // B13
    }

    // ---- layer 1 order 0 ----
    PHASE_BJAC(g_X1, g_A);         // B14
    PHASE_JAC(g_A, g_A, g_B);      // B15
    PHASE_JAC(g_B, g_A, g_C);      // B16
    PHASE_JAC(g_C, g_A, g_B);      // B17
    PHASE_JAC(g_B, g_A, g_C);      // B18
    PHASE_JAC(g_C, g_A, g_Y1);     // B19

    // ---- layer 1 order 1 ----
    PHASE_BJAC(g_Y1, g_A);         // B20
    PHASE_JAC(g_A, g_A, g_B);      // B21
    PHASE_JAC(g_B, g_A, g_C);      // B22
    PHASE_JAC(g_C, g_A, g_B);      // B23
    PHASE_JAC(g_B, g_A, g_C);      // B24
    // fused last jac + outgemm + score/keys (X2 stays in registers)
    {
        float* sW = (float*)s_raw;
        for (int t = tid; t < FF * FF; t += TPB) {
            int f = t >> 5, k = t & 31;
            sW[k * FF + f]        = __ldg(Wr1 + t);
            sW[1024 + k * FF + f] = __ldg(Wc1a + t);
            sW[2048 + k * FF + f] = __ldg(Wc1b + t);
        }
        __syncthreads();
        if (wid < nrows) {
            int r = r0 + wid;
            float y2; ROW_JAC(g_C, g_A, y2);
            float y1 = __ldcg(g_Y1 + r * FF + lane);
            float xo = __ldcg(g_X1 + r * FF + lane);
            float acc = 0.f;
#pragma unroll
            for (int k = 0; k < FF; ++k) {
                float xv  = __shfl_sync(0xffffffffu, xo, k);
                float y1v = __shfl_sync(0xffffffffu, y1, k);
                float y2v = __shfl_sync(0xffffffffu, y2, k);
                acc += xv * sW[k * FF + lane]
                     + 2.f * y1v * sW[1024 + k * FF + lane]
                     + 2.f * y2v * sW[2048 + k * FF + lane];
            }
            myxout = fmaxf(acc, 0.f);
            float v = myxout * pwv;
#pragma unroll
            for (int o = 16; o > 0; o >>= 1) v += __shfl_xor_sync(0xffffffffu, v, o);
            myscore = tanhf(v / pnorm);
            if (lane == 0)
                g_keys[r] = ((unsigned long long)f2ord(myscore) << 32)
                          | (unsigned long long)(0xFFFFFFFFu - (unsigned int)r);
        }
        gsync();   // B25
    }

    // ---- rank + weighted partial sums + counter re-zero + ARRIVE (no poll) ----
    {
        unsigned long long* sk = (unsigned long long*)s_raw;
        float* spart = (float*)(s_raw + 24000);
        for (int i = tid; i < NN; i += TPB)
            sk[i] = __ldcg((const unsigned long long*)(g_keys + i));
        if (tid < nrows) { g_deg[r0 + tid] = 0; g_rcnt[r0 + tid] = 0; }
        __syncthreads();
        float contrib = 0.f;
        if (wid < nrows) {
            int r = r0 + wid;
            unsigned long long ki = ((unsigned long long)f2ord(myscore) << 32)
                                  | (unsigned long long)(0xFFFFFFFFu - (unsigned int)r);
            int c2 = 0;
            for (int j = lane; j < NN; j += 32) c2 += (sk[j] < ki) ? 1 : 0;
#pragma unroll
            for (int o = 16; o > 0; o >>= 1) c2 += __shfl_xor_sync(0xffffffffu, c2, o);
            float coef = (c2 < EXCL && myscore < 0.f) ? 0.f : myscore;
            contrib = coef * myxout;
        }
        spart[wid * FF + lane] = contrib;
        __syncthreads();
        if (wid == 0) {
            float t = 0.f;
#pragma unroll
            for (int q = 0; q < NWARP; ++q) t += spart[q * FF + lane];
            g_part[bid * FF + lane] = t;
        }
        // final arrival: release my g_part, detect last arriver; NO polling
        __syncthreads();
        if (tid == 0) {
            unsigned int old;
            asm volatile("atom.acq_rel.gpu.add.u32 %0, [%1], 1;"
                         : "=r"(old) : "l"(&g_ctr) : "memory");
            s_last = (old % GRID == GRID - 1u) ? 1 : 0;
        }
        __syncthreads();
    }

    // ---- LAST ARRIVER ONLY: final reduce + linear + run-epoch bump ----
    if (s_last && wid == 0) {
        // all 147 other blocks' release-arrives happened-before our acq_rel RMW
        float t = 0.f;
        for (int b = 0; b < GRID; ++b)
            t += __ldcg(g_part + b * FF + lane);
        float* sg = (float*)(s_raw + 24000);
        sg[lane] = t * (1.0f / KSELF);
        __syncwarp();
        if (lane < 8) {
            float o = __ldg(lb + lane);
#pragma unroll
            for (int f = 0; f < FF; ++f) o += sg[f] * __ldg(lw + lane * FF + f);
            out[lane] = o;
        }
        if (lane == 0) g_run = gen;   // epoch for next run (runs serialize at kernel boundary)
    }
}

// ---------------- host side ----------------
extern "C" void kernel_launch(void* const* d_in, const int* in_sizes, int n_in,
                              void* d_out, int out_size) {
    const float* x     = (const float*)d_in[0];
    const int*   ei    = (const int*)d_in[1];
    const float* h     = (const float*)d_in[2];
    const float* alpha = (const float*)d_in[3];
    const float* Wr0   = (const float*)d_in[4];
    const float* Wc0a  = (const float*)d_in[5];
    const float* Wc0b  = (const float*)d_in[6];
    const float* Wr1   = (const float*)d_in[7];
    const float* Wc1a  = (const float*)d_in[8];
    const float* Wc1b  = (const float*)d_in[9];
    const float* pw    = (const float*)d_in[10];
    const float* lw    = (const float*)d_in[11];
    const float* lb    = (const float*)d_in[12];

    cayley_all<<<GRID, TPB>>>(x, ei, h, alpha, Wr0, Wc0a, Wc0b,
                              Wr1, Wc1a, Wc1b, pw, lw, lb, (float*)d_out);
}

// round 16
// speedup vs baseline: 3.2421x; 1.0003x over previous
#include <cuda_runtime.h>
#include <math.h>

#define NN 3000
#define EE 48000
#define FF 32
#define GRID 120
#define TPB 800            // 25 warps, 1 row per warp, 25 rows per block (exact)
#define NWARP 25
#define EXCL 1200
#define KSELF 10800.0f
#define ROWCAP 64
#define NRMAX 25

// ---------------- static global state ----------------
__device__ unsigned int g_gen[(size_t)NN * NN];   // 36 MB dedup generations (never zeroed)
__device__ unsigned int g_run;                     // run epoch (bumped by finalizer)
__device__ int g_deg[NN];                          // re-zeroed each run by owners
__device__ int g_rcnt[NN];
__device__ unsigned short g_cols[NN * ROWCAP];
__device__ float g_A[NN * FF];
__device__ float g_B[NN * FF];
__device__ float g_C[NN * FF];
__device__ float g_Y1[NN * FF];
__device__ float g_X1[NN * FF];
__device__ unsigned long long g_keys[NN];
__device__ float g_part[GRID * FF];
__device__ unsigned int g_ctr;                     // ticket barrier counter (monotonic)

// ---------------- R5 ticket barrier (measured optimum) ----------------
__device__ __forceinline__ void gsync() {
    __syncthreads();
    if (threadIdx.x == 0) {
        unsigned int old;
        asm volatile("atom.release.gpu.add.u32 %0, [%1], 1;"
                     : "=r"(old) : "l"(&g_ctr) : "memory");
        unsigned int target = old - (old % GRID) + GRID;   // next multiple of GRID
        unsigned int v;
        do {
            asm volatile("ld.acquire.gpu.u32 %0, [%1];" : "=r"(v) : "l"(&g_ctr) : "memory");
        } while ((int)(v - target) < 0);
    }
    __syncthreads();
}

__device__ __forceinline__ unsigned int f2ord(float f) {
    unsigned int u = __float_as_uint(f);
    return (u & 0x80000000u) ? ~u : (u | 0x80000000u);
}

// ---------------- the one persistent kernel ----------------
__global__ void __launch_bounds__(TPB, 1)
cayley_all(const float* __restrict__ x, const int* __restrict__ ei,
           const float* __restrict__ ph, const float* __restrict__ palpha,
           const float* __restrict__ Wr0, const float* __restrict__ Wc0a,
           const float* __restrict__ Wc0b, const float* __restrict__ Wr1,
           const float* __restrict__ Wc1a, const float* __restrict__ Wc1b,
           const float* __restrict__ pw, const float* __restrict__ lw,
           const float* __restrict__ lb, float* __restrict__ out) {
    // s_raw: 6 weight matrices (24576B) during phases; keys (24000B) alias at rank; partials after
    __shared__ __align__(16) unsigned char s_raw[24576 + NWARP * FF * 4];
    __shared__ __align__(8) float2 s_ew[NRMAX * ROWCAP];   // (byte-offset bits, weight) per edge
    __shared__ int s_cnt[NRMAX];
    __shared__ float s_sinv[NRMAX];
    __shared__ int s_last;

    const int tid  = threadIdx.x;
    const int lane = tid & 31;
    const int wid  = tid >> 5;
    const int bid  = blockIdx.x;

    const int r0    = bid * NRMAX;            // exact 25 rows per block
    const int nrows = NRMAX;

    const unsigned int gen = g_run + 1u;      // unique per run (runs serialize)

    const int* rowp = ei;
    const int* colp = ei + EE;
    const float hh = __ldg(ph);
    const float aa = __ldg(palpha);

    // pool_w norm
    float pwv = __ldg(pw + lane);
    float nv = pwv * pwv;
#pragma unroll
    for (int o = 16; o > 0; o >>= 1) nv += __shfl_xor_sync(0xffffffffu, nv, o);
    const float pnorm = sqrtf(nv);

    // ---- stage all 6 weight matrices (transposed) once; ordered before use by B1 ----
    {
        float* sW = (float*)s_raw;
        for (int t = tid; t < FF * FF; t += TPB) {
            int f = t >> 5, k = t & 31;
            sW[k * FF + f]        = __ldg(Wr0 + t);
            sW[1024 + k * FF + f] = __ldg(Wc0a + t);
            sW[2048 + k * FF + f] = __ldg(Wc0b + t);
            sW[3072 + k * FF + f] = __ldg(Wr1 + t);
            sW[4096 + k * FF + f] = __ldg(Wc1a + t);
            sW[5120 + k * FF + f] = __ldg(Wc1b + t);
        }
    }

    // ---- S1: distributed edge build (1 edge / thread; 120*800 = 96000 >= EE) ----
    {
        int e = bid * TPB + tid;
        if (e < EE) {
            int r = __ldg(rowp + e), c = __ldg(colp + e);
            atomicAdd(&g_deg[r], 1);                              // degree with multiplicity
            unsigned int old = atomicMax(&g_gen[(size_t)r * NN + c], gen);
            if (old < gen) {                                      // first occurrence this run
                int pos = atomicAdd(&g_rcnt[r], 1);
                if (pos < ROWCAP) g_cols[r * ROWCAP + pos] = (unsigned short)c;
            }
        }
    }
    gsync();   // B1

    // ---- CSR -> smem + weights ----
    {
        if (tid < nrows) {
            int r = r0 + tid;
            int c2 = g_rcnt[r];
            s_cnt[tid] = c2 > ROWCAP ? ROWCAP : c2;
            s_sinv[tid] = 1.0f / ((float)g_deg[r] - aa);
        }
        __syncthreads();
        for (int idx = tid; idx < NRMAX * ROWCAP; idx += TPB) {
            int lr = idx >> 6, j = idx & 63;
            if (j < s_cnt[lr]) {
                int c = (int)g_cols[(r0 + lr) * ROWCAP + j];
                float w = 1.0f / (((float)g_deg[c] - aa) * hh);   // invD[col]
                s_ew[idx] = make_float2(__int_as_float(c * (FF * 4)), w);
            }
        }
        __syncthreads();
    }

#define ROW_BJAC(IN, RES) do { \
        int r = r0 + wid; \
        float diag = __ldcg((IN) + r * FF + lane); \
        int cnt = s_cnt[wid]; \
        const float2* ep = s_ew + wid * ROWCAP; \
        float acc = 0.f; \
        _Pragma("unroll 8") \
        for (int j = 0; j < cnt; ++j) { \
            float2 e = ep[j]; \
            acc += __ldcg((const float*)((const char*)(IN) + __float_as_int(e.x)) + lane); \
        } \
        RES = diag - s_sinv[wid] * acc; \
    } while (0)

#define ROW_JAC(YK, BJ, RES) do { \
        int r = r0 + wid; \
        float bjv = __ldcg((BJ) + r * FF + lane); \
        int cnt = s_cnt[wid]; \
        const float2* ep = s_ew + wid * ROWCAP; \
        float acc = 0.f; \
        _Pragma("unroll 8") \
        for (int j = 0; j < cnt; ++j) { \
            float2 e = ep[j]; \
            acc += e.y * __ldcg((const float*)((const char*)(YK) + __float_as_int(e.x)) + lane); \
        } \
        RES = acc + bjv; \
    } while (0)

#define PHASE_BJAC(IN, OUT) do { \
        { float rres; ROW_BJAC(IN, rres); \
          OUT[(r0 + wid) * FF + lane] = rres; } \
        gsync(); } while (0)

#define PHASE_JAC(YK, BJ, OUT) do { \
        { float rres; ROW_JAC(YK, BJ, rres); \
          OUT[(r0 + wid) * FF + lane] = rres; } \
        gsync(); } while (0)

    float myscore = 0.f, myxout = 0.f;
    const float* sW = (const float*)s_raw;

    // ---- layer 0 order 0 ----
    PHASE_BJAC(x, g_A);            // B2
    PHASE_JAC(g_A, g_A, g_B);      // B3
    PHASE_JAC(g_B, g_A, g_C);      // B4
    PHASE_JAC(g_C, g_A, g_B);      // B5
    PHASE_JAC(g_B, g_A, g_C);      // B6
    PHASE_JAC(g_C, g_A, g_Y1);     // B7

    // ---- layer 0 order 1 ----
    PHASE_BJAC(g_Y1, g_A);         // B8
    PHASE_JAC(g_A, g_A, g_B);      // B9
    PHASE_JAC(g_B, g_A, g_C);      // B10
    PHASE_JAC(g_C, g_A, g_B);      // B11
    PHASE_JAC(g_B, g_A, g_C);      // B12
    // fused last jac + outgemm -> X1
    {
        {
            int r = r0 + wid;
            float y2; ROW_JAC(g_C, g_A, y2);
            float y1 = __ldcg(g_Y1 + r * FF + lane);
            float xo = __ldg(x + r * FF + lane);
            float acc = 0.f;
#pragma unroll
            for (int k = 0; k < FF; ++k) {
                float xv  = __shfl_sync(0xffffffffu, xo, k);
                float y1v = __shfl_sync(0xffffffffu, y1, k);
                float y2v = __shfl_sync(0xffffffffu, y2, k);
                acc += xv * sW[k * FF + lane]
                     + 2.f * y1v * sW[1024 + k * FF + lane]
                     + 2.f * y2v * sW[2048 + k * FF + lane];
            }
            g_X1[r * FF + lane] = fmaxf(acc, 0.f);
        }
        gsync();   // B13
    }

    // ---- layer 1 order 0 ----
    PHASE_BJAC(g_X1, g_A);         // B14
    PHASE_JAC(g_A, g_A, g_B);      // B15
    PHASE_JAC(g_B, g_A, g_C);      // B16
    PHASE_JAC(g_C, g_A, g_B);      // B17
    PHASE_JAC(g_B, g_A, g_C);      // B18
    PHASE_JAC(g_C, g_A, g_Y1);     // B19

    // ---- layer 1 order 1 ----
    PHASE_BJAC(g_Y1, g_A);         // B20
    PHASE_JAC(g_A, g_A, g_B);      // B21
    PHASE_JAC(g_B, g_A, g_C);      // B22
    PHASE_JAC(g_C, g_A, g_B);      // B23
    PHASE_JAC(g_B, g_A, g_C);      // B24
    // fused last jac + outgemm + score/keys (X2 stays in registers)
    {
        {
            int r = r0 + wid;
            float y2; ROW_JAC(g_C, g_A, y2);
            float y1 = __ldcg(g_Y1 + r * FF + lane);
            float xo = __ldcg(g_X1 + r * FF + lane);
            float acc = 0.f;
#pragma unroll
            for (int k = 0; k < FF; ++k) {
                float xv  = __shfl_sync(0xffffffffu, xo, k);
                float y1v = __shfl_sync(0xffffffffu, y1, k);
                float y2v = __shfl_sync(0xffffffffu, y2, k);
                acc += xv * sW[3072 + k * FF + lane]
                     + 2.f * y1v * sW[4096 + k * FF + lane]
                     + 2.f * y2v * sW[5120 + k * FF + lane];
            }
            myxout = fmaxf(acc, 0.f);
            float v = myxout * pwv;
#pragma unroll
            for (int o = 16; o > 0; o >>= 1) v += __shfl_xor_sync(0xffffffffu, v, o);
            myscore = tanhf(v / pnorm);
            if (lane == 0)
                g_keys[r] = ((unsigned long long)f2ord(myscore) << 32)
                          | (unsigned long long)(0xFFFFFFFFu - (unsigned int)r);
        }
        gsync();   // B25
    }

    // ---- rank + weighted partial sums + counter re-zero + ARRIVE (no poll) ----
    {
        unsigned long long* sk = (unsigned long long*)s_raw;   // weights dead now
        float* spart = (float*)(s_raw + 24576);
        for (int i = tid; i < NN; i += TPB)
            sk[i] = __ldcg((const unsigned long long*)(g_keys + i));
        if (tid < nrows) { g_deg[r0 + tid] = 0; g_rcnt[r0 + tid] = 0; }
        __syncthreads();
        float contrib = 0.f;
        {
            int r = r0 + wid;
            unsigned long long ki = ((unsigned long long)f2ord(myscore) << 32)
                                  | (unsigned long long)(0xFFFFFFFFu - (unsigned int)r);
            int c2 = 0;
            for (int j = lane; j < NN; j += 32) c2 += (sk[j] < ki) ? 1 : 0;
#pragma unroll
            for (int o = 16; o > 0; o >>= 1) c2 += __shfl_xor_sync(0xffffffffu, c2, o);
            float coef = (c2 < EXCL && myscore < 0.f) ? 0.f : myscore;
            contrib = coef * myxout;
        }
        spart[wid * FF + lane] = contrib;
        __syncthreads();
        if (wid == 0) {
            float t = 0.f;
#pragma unroll
            for (int q = 0; q < NWARP; ++q) t += spart[q * FF + lane];
            g_part[bid * FF + lane] = t;
        }
        // final arrival: release my g_part, detect last arriver; NO polling
        __syncthreads();
        if (tid == 0) {
            unsigned int old;
            asm volatile("atom.acq_rel.gpu.add.u32 %0, [%1], 1;"
                         : "=r"(old) : "l"(&g_ctr) : "memory");
            s_last = (old % GRID == GRID - 1u) ? 1 : 0;
        }
        __syncthreads();
    }

    // ---- LAST ARRIVER ONLY: final reduce + linear + run-epoch bump ----
    if (s_last && wid == 0) {
        float t = 0.f;
        for (int b = 0; b < GRID; ++b)
            t += __ldcg(g_part + b * FF + lane);
        float* sg = (float*)(s_raw + 24576);
        sg[lane] = t * (1.0f / KSELF);
        __syncwarp();
        if (lane < 8) {
            float o = __ldg(lb + lane);
#pragma unroll
            for (int f = 0; f < FF; ++f) o += sg[f] * __ldg(lw + lane * FF + f);
            out[lane] = o;
        }
        if (lane == 0) g_run = gen;   // epoch for next run (runs serialize at kernel boundary)
    }
}

// ---------------- host side ----------------
extern "C" void kernel_launch(void* const* d_in, const int* in_sizes, int n_in,
                              void* d_out, int out_size) {
    const float* x     = (const float*)d_in[0];
    const int*   ei    = (const int*)d_in[1];
    const float* h     = (const float*)d_in[2];
    const float* alpha = (const float*)d_in[3];
    const float* Wr0   = (const float*)d_in[4];
    const float* Wc0a  = (const float*)d_in[5];
    const float* Wc0b  = (const float*)d_in[6];
    const float* Wr1   = (const float*)d_in[7];
    const float* Wc1a  = (const float*)d_in[8];
    const float* Wc1b  = (const float*)d_in[9];
    const float* pw    = (const float*)d_in[10];
    const float* lw    = (const float*)d_in[11];
    const float* lb    = (const float*)d_in[12];

    cayley_all<<<GRID, TPB>>>(x, ei, h, alpha, Wr0, Wc0a, Wc0b,
                              Wr1, Wc1a, Wc1b, pw, lw, lb, (float*)d_out);
}